// round 16
// baseline (speedup 1.0000x reference)
#include <cuda_runtime.h>
#include <cuda_bf16.h>
#include <cstdint>

// out = feat @ Wv + bv
//
// The reference's softmax over axis=-2 (j) followed by einsum('ijk,ik->ik')
// (a sum over j) makes the attention-weight branch sum to exactly 1 per
// (i,k), so out[i,k] == v[i,k] == (feat @ Wv + bv)[i,k].
//
// feat: [N=1024, C=256] f32   (d_in[0])
// Wv:   [C, C]          f32   (d_in[9])
// bv:   [C]             f32   (d_in[10])
// out:  [N, C]          f32
//
// Split precision on tensor cores (tcgen05 rejected by compute_103):
//   x ~= hi + lo (bf16);  A*B ~= Ah*Bh + Ah*Bl + Al*Bh   (fp32 accum)
// R16: 32x32 tile, 256 threads (8 warps, one m16n8 tile each), 3 CTAs/SM
// (launch_bounds(256,3); smem 74.9KB x3 = 224.6KB fits). 24 warps/SM of
// latency tolerance for the fill phase that bound R11-R15.

namespace {

constexpr int Cdim = 256;

// smem strides (ldmatrix conflict-free, validated since R12):
//  A rows 264 bf16 = 528 B; B rows 40 bf16 = 80 B
constexpr uint32_t A_STRIDE_B = 528;
constexpr uint32_t B_STRIDE_B = 80;
constexpr uint32_t SM_AHI  = 0;
constexpr uint32_t SM_ALO  = SM_AHI + 32 * A_STRIDE_B;    // 16896
constexpr uint32_t SM_BHI  = SM_ALO + 32 * A_STRIDE_B;    // 33792
constexpr uint32_t SM_BLO  = SM_BHI + 256 * B_STRIDE_B;   // 54272
constexpr uint32_t SM_BIAS = SM_BLO + 256 * B_STRIDE_B;   // 74752
constexpr uint32_t SMEM_BYTES = SM_BIAS + 128;            // 74880

#define LDSM_X4(r0, r1, r2, r3, addr)                                        \
    asm volatile("ldmatrix.sync.aligned.m8n8.x4.shared.b16 {%0,%1,%2,%3}, [%4];" \
                 : "=r"(r0), "=r"(r1), "=r"(r2), "=r"(r3) : "r"(addr))

#define LDSM_X2T(r0, r1, addr)                                               \
    asm volatile("ldmatrix.sync.aligned.m8n8.x2.trans.shared.b16 {%0,%1}, [%2];" \
                 : "=r"(r0), "=r"(r1) : "r"(addr))

#define MMA_BF16(c, a0, a1, a2, a3, b0, b1)                                  \
    asm volatile("mma.sync.aligned.m16n8k16.row.col.f32.bf16.bf16.f32 "      \
                 "{%0,%1,%2,%3}, {%4,%5,%6,%7}, {%8,%9}, {%0,%1,%2,%3};"     \
                 : "+f"((c)[0]), "+f"((c)[1]), "+f"((c)[2]), "+f"((c)[3])    \
                 : "r"(a0), "r"(a1), "r"(a2), "r"(a3), "r"(b0), "r"(b1))

__device__ __forceinline__ uint32_t smem_u32(const void* p) {
    uint32_t a;
    asm("{ .reg .u64 t; cvta.to.shared.u64 t, %1; cvt.u32.u64 %0, t; }"
        : "=r"(a) : "l"(p));
    return a;
}

__device__ __forceinline__ uint32_t pack_bf2(float a, float b) {
    uint32_t r;
    asm("cvt.rn.bf16x2.f32 %0, %1, %2;" : "=r"(r) : "f"(b), "f"(a));
    return r;
}
// split a float4 into hi (bf16x2 pair) and lo (residual bf16x2 pair)
__device__ __forceinline__ void split4(float4 f, uint2& hi, uint2& lo) {
    hi.x = pack_bf2(f.x, f.y);
    hi.y = pack_bf2(f.z, f.w);
    const float hx = __uint_as_float(hi.x << 16);
    const float hy = __uint_as_float(hi.x & 0xFFFF0000u);
    const float hz = __uint_as_float(hi.y << 16);
    const float hw = __uint_as_float(hi.y & 0xFFFF0000u);
    lo.x = pack_bf2(f.x - hx, f.y - hy);
    lo.y = pack_bf2(f.z - hz, f.w - hw);
}

// CTA: 32(M) x 32(N) tile, full K=256. 256 threads = 8 warps.
// Warp w: m-strip (w>>2)*16, n8-tile (w&3). Grid (8, 32) = 256 CTAs.

__global__ __launch_bounds__(256, 3)
void vgemm_mma_kernel(const float* __restrict__ feat,  // [1024, 256]
                      const float* __restrict__ Wv,    // [256, 256]
                      const float* __restrict__ bias,  // [256]
                      float* __restrict__ O)           // [1024, 256]
{
    extern __shared__ char smem[];
    const uint32_t sb = smem_u32(smem);

    const int tid  = (int)threadIdx.x;   // 0..255
    const int warp = tid >> 5;           // 0..7
    const int lane = tid & 31;
    const int row0 = (int)blockIdx.y * 32;
    const int col0 = (int)blockIdx.x * 32;

    // ---- stage bias ----
    if (tid < 8) {
        reinterpret_cast<float4*>(smem + SM_BIAS)[tid] =
            reinterpret_cast<const float4*>(bias + col0)[tid];
    }

    // ---- load + split A: 32 x 256 f32 = 2048 float4; 8 per thread ----
    #pragma unroll
    for (int it = 0; it < 8; it++) {
        const int idx = it * 256 + tid;
        const int m   = idx >> 6;          // 64 float4 per row
        const int c4  = idx & 63;
        const float4 f = *reinterpret_cast<const float4*>(
            &feat[(row0 + m) * Cdim + c4 * 4]);
        uint2 hi, lo;
        split4(f, hi, lo);
        const uint32_t off = (uint32_t)m * A_STRIDE_B + (uint32_t)c4 * 8;
        *reinterpret_cast<uint2*>(smem + SM_AHI + off) = hi;
        *reinterpret_cast<uint2*>(smem + SM_ALO + off) = lo;
    }

    // ---- load + split B: Wv[k][col0..col0+32), 2048 float4; 8 per thread ----
    #pragma unroll
    for (int it = 0; it < 8; it++) {
        const int idx = it * 256 + tid;
        const int k   = idx >> 3;          // 8 float4 per row
        const int c4  = idx & 7;
        const float4 f = *reinterpret_cast<const float4*>(
            &Wv[k * Cdim + col0 + c4 * 4]);
        uint2 hi, lo;
        split4(f, hi, lo);
        const uint32_t off = (uint32_t)k * B_STRIDE_B + (uint32_t)c4 * 8;
        *reinterpret_cast<uint2*>(smem + SM_BHI + off) = hi;
        *reinterpret_cast<uint2*>(smem + SM_BLO + off) = lo;
    }

    __syncthreads();

    // ---- tensor-core mainloop: one m16n8 tile per warp ----
    const int m0 = (warp >> 2) * 16;      // m-strip: 0 or 16
    const int nb = (warp & 3) * 8;        // n8-tile column offset
    float acc[4] = {0.f, 0.f, 0.f, 0.f};

    const uint32_t aHiBase = sb + SM_AHI +
        (uint32_t)(m0 + (lane & 15)) * A_STRIDE_B + (uint32_t)(lane >> 4) * 16;
    const uint32_t aLoBase = aHiBase + (SM_ALO - SM_AHI);
    const uint32_t bHiBase = sb + SM_BHI +
        (uint32_t)(lane & 15) * B_STRIDE_B + (uint32_t)nb * 2;

    #pragma unroll
    for (int ks = 0; ks < 16; ks++) {
        uint32_t ah0, ah1, ah2, ah3, al0, al1, al2, al3;
        LDSM_X4(ah0, ah1, ah2, ah3, aHiBase + (uint32_t)ks * 32);
        LDSM_X4(al0, al1, al2, al3, aLoBase + (uint32_t)ks * 32);

        const uint32_t ba = bHiBase + (uint32_t)ks * (16 * B_STRIDE_B);
        uint32_t bh0, bh1, bl0, bl1;
        LDSM_X2T(bh0, bh1, ba);
        LDSM_X2T(bl0, bl1, ba + (SM_BLO - SM_BHI));

        MMA_BF16(acc, ah0, ah1, ah2, ah3, bh0, bh1);
        MMA_BF16(acc, ah0, ah1, ah2, ah3, bl0, bl1);
        MMA_BF16(acc, al0, al1, al2, al3, bh0, bh1);
    }

    // ---- epilogue: bias add + stores (canonical m16n8 D mapping) ----
    const float* bs = reinterpret_cast<const float*>(smem + SM_BIAS);
    const int g  = lane >> 2;
    const int tc = (lane & 3) * 2;
    const int r1 = row0 + m0 + g;
    const int r2 = r1 + 8;
    const int n  = nb + tc;
    float2 o1, o2;
    o1.x = acc[0] + bs[n];
    o1.y = acc[1] + bs[n + 1];
    o2.x = acc[2] + bs[n];
    o2.y = acc[3] + bs[n + 1];
    *reinterpret_cast<float2*>(&O[r1 * Cdim + col0 + n]) = o1;
    *reinterpret_cast<float2*>(&O[r2 * Cdim + col0 + n]) = o2;
}

} // namespace

extern "C" void kernel_launch(void* const* d_in, const int* in_sizes, int n_in,
                              void* d_out, int out_size)
{
    const float* feat = (const float*)d_in[0];
    const float* Wv   = (const float*)d_in[9];
    const float* bv   = (const float*)d_in[10];
    float* out        = (float*)d_out;

    cudaFuncSetAttribute(vgemm_mma_kernel,
                         cudaFuncAttributeMaxDynamicSharedMemorySize,
                         (int)SMEM_BYTES);
    dim3 grid(8, 32);   // 8 N-tiles x 32 M-tiles = 256 CTAs (~2-3/SM)
    vgemm_mma_kernel<<<grid, 256, SMEM_BYTES>>>(feat, Wv, bv, out);
}